// round 3
// baseline (speedup 1.0000x reference)
#include <cuda_runtime.h>
#include <math.h>

#define NTOK 4096
#define DM   256
#define NH   8
#define DK   32
#define NSEG 16
#define LMAX 512            // max segment length supported in smem (mean 256, sd ~15.5 -> 16 sigma headroom)
#define NKMAX (LMAX/32)     // 16 key-groups of 32
#define RPAD 36             // smem row pitch in floats (32 data + 4 pad) -> conflict-free float4 reads

// Scratch (device globals: no allocations allowed)
__device__ float g_Q[NTOK*DM];
__device__ float g_K[NTOK*DM];
__device__ float g_V[NTOK*DM];
__device__ float g_C[NTOK*DM];   // attention context before output projection

// ---------------------------------------------------------------------------
// Vectorized zero fill (the attn output is 537MB, ~94% exact zeros)
// ---------------------------------------------------------------------------
__global__ void zero_kernel(float* __restrict__ out, long long n) {
    long long i      = (long long)blockIdx.x * blockDim.x + threadIdx.x;
    long long stride = (long long)gridDim.x * blockDim.x;
    long long n4     = n >> 2;
    float4 z = make_float4(0.f, 0.f, 0.f, 0.f);
    float4* o4 = (float4*)out;
    for (long long j = i; j < n4; j += stride) o4[j] = z;
    long long tail = n4 << 2;
    if (i < (n - tail)) out[tail + i] = 0.f;
}

// ---------------------------------------------------------------------------
// C[m, j] = sum_d A[m, d] * W[j, d] + bias[j]   (torch Linear: x @ W.T + b)
// A: [4096, 256] row-major, W: [256, 256] row-major. 64x64 block tile,
// 256 threads, 4x4 microtile, k-chunk 16.
// ---------------------------------------------------------------------------
__global__ void gemm_bias_kernel(const float* __restrict__ A,
                                 const float* __restrict__ W,
                                 const float* __restrict__ bias,
                                 float* __restrict__ C) {
    __shared__ float As[16][68];   // [k][m]
    __shared__ float Bs[16][68];   // [k][j]
    int tid = threadIdx.x;
    int tx = tid & 15, ty = tid >> 4;
    int m0 = blockIdx.y << 6, j0 = blockIdx.x << 6;
    int lr = tid >> 2;           // 0..63 row within tile
    int lk = (tid & 3) << 2;     // 0,4,8,12 k within chunk

    float acc[4][4];
#pragma unroll
    for (int i = 0; i < 4; i++)
#pragma unroll
        for (int j = 0; j < 4; j++) acc[i][j] = 0.f;

    for (int kc = 0; kc < DM; kc += 16) {
        float4 a = *(const float4*)&A[(size_t)(m0 + lr) * DM + kc + lk];
        float4 b = *(const float4*)&W[(size_t)(j0 + lr) * DM + kc + lk];
        As[lk + 0][lr] = a.x; As[lk + 1][lr] = a.y; As[lk + 2][lr] = a.z; As[lk + 3][lr] = a.w;
        Bs[lk + 0][lr] = b.x; Bs[lk + 1][lr] = b.y; Bs[lk + 2][lr] = b.z; Bs[lk + 3][lr] = b.w;
        __syncthreads();
#pragma unroll
        for (int k = 0; k < 16; k++) {
            float av[4], bv[4];
#pragma unroll
            for (int i = 0; i < 4; i++) av[i] = As[k][(ty << 2) + i];
#pragma unroll
            for (int j = 0; j < 4; j++) bv[j] = Bs[k][(tx << 2) + j];
#pragma unroll
            for (int i = 0; i < 4; i++)
#pragma unroll
                for (int j = 0; j < 4; j++) acc[i][j] += av[i] * bv[j];
        }
        __syncthreads();
    }

    int j = j0 + (tx << 2);
    float4 bb = *(const float4*)&bias[j];
#pragma unroll
    for (int i = 0; i < 4; i++) {
        int m = m0 + (ty << 2) + i;
        float4 r = make_float4(acc[i][0] + bb.x, acc[i][1] + bb.y,
                               acc[i][2] + bb.z, acc[i][3] + bb.w);
        *(float4*)&C[(size_t)m * DM + j] = r;
    }
}

// ---------------------------------------------------------------------------
// Attention: one block per (segment, head). K/V staged in smem (zero padded
// to a multiple of 32 rows). Each warp processes 4 queries at a time; scores
// kept in registers (<= 16 key-groups), exact softmax, normalized probs
// written into the block-diagonal slice of the attn output, context into g_C.
// ---------------------------------------------------------------------------
__global__ void __launch_bounds__(256, 1)
attn_kernel(const int* __restrict__ batch_q,
            const int* __restrict__ batch_kv,
            float* __restrict__ attn_out) {   // base of attn region of d_out
    extern __shared__ float sm[];
    float* Ks = sm;                       // LMAX * RPAD
    float* Vs = sm + LMAX * RPAD;         // LMAX * RPAD
    float* Qs = sm + 2 * LMAX * RPAD;     // 32 * RPAD
    __shared__ int rng[4];

    int seg = blockIdx.x, h = blockIdx.y;
    int tid = threadIdx.x, lane = tid & 31, warp = tid >> 5;

    if (tid < 4) {
        const int* arr = (tid < 2) ? batch_q : batch_kv;
        int target = seg + (tid & 1);
        int lo = 0, hi = NTOK;
        while (lo < hi) { int mid = (lo + hi) >> 1; if (arr[mid] < target) lo = mid + 1; else hi = mid; }
        rng[tid] = lo;
    }
    __syncthreads();
    int qstart = rng[0], qend = rng[1], kstart = rng[2], kend = rng[3];
    int len = kend - kstart;
    if (len <= 0 || qend <= qstart) return;
    if (len > LMAX) len = LMAX;           // unreachable for this distribution
    int nk = (len + 31) >> 5;
    int rows = nk << 5;

    // stage K, V (zero padded rows beyond len)
    for (int idx = tid; idx < rows * DK; idx += 256) {
        int k = idx >> 5, d = idx & 31;
        float kv = 0.f, vv = 0.f;
        if (k < len) {
            size_t g = (size_t)(kstart + k) * DM + h * DK + d;
            kv = g_K[g]; vv = g_V[g];
        }
        Ks[k * RPAD + d] = kv;
        Vs[k * RPAD + d] = vv;
    }

    const float scale = 0.17677669529663689f;   // 1/sqrt(32)

    for (int q0 = qstart; q0 < qend; q0 += 32) {
        __syncthreads();   // protect Qs reuse
        for (int idx = tid; idx < 32 * DK; idx += 256) {
            int r = idx >> 5, d = idx & 31;
            int q = q0 + r;
            Qs[r * RPAD + d] = (q < qend) ? g_Q[(size_t)q * DM + h * DK + d] : 0.f;
        }
        __syncthreads();

        int qb = warp << 2;   // this warp's 4 queries: q0+qb .. q0+qb+3
        float S[4][NKMAX];

        // ---- scores: each lane owns key k = 32*i + lane, 4 queries ----
#pragma unroll
        for (int i = 0; i < NKMAX; i++) {
            if (i >= nk) break;
            int k = (i << 5) + lane;
            const float4* Kr = (const float4*)&Ks[k * RPAD];
            float a0 = 0.f, a1 = 0.f, a2 = 0.f, a3 = 0.f;
#pragma unroll
            for (int d4 = 0; d4 < 8; d4++) {
                float4 kv = Kr[d4];
                float4 v0 = *(const float4*)&Qs[(qb + 0) * RPAD + (d4 << 2)];
                float4 v1 = *(const float4*)&Qs[(qb + 1) * RPAD + (d4 << 2)];
                float4 v2 = *(const float4*)&Qs[(qb + 2) * RPAD + (d4 << 2)];
                float4 v3 = *(const float4*)&Qs[(qb + 3) * RPAD + (d4 << 2)];
                a0 += kv.x * v0.x + kv.y * v0.y + kv.z * v0.z + kv.w * v0.w;
                a1 += kv.x * v1.x + kv.y * v1.y + kv.z * v1.z + kv.w * v1.w;
                a2 += kv.x * v2.x + kv.y * v2.y + kv.z * v2.z + kv.w * v2.w;
                a3 += kv.x * v3.x + kv.y * v3.y + kv.z * v3.z + kv.w * v3.w;
            }
            bool ok = (k < len);
            S[0][i] = ok ? a0 * scale : -1e30f;
            S[1][i] = ok ? a1 * scale : -1e30f;
            S[2][i] = ok ? a2 * scale : -1e30f;
            S[3][i] = ok ? a3 * scale : -1e30f;
        }

        // ---- softmax (exact, two register passes) ----
        float inv[4];
#pragma unroll
        for (int qi = 0; qi < 4; qi++) {
            float m = -1e30f;
#pragma unroll
            for (int i = 0; i < NKMAX; i++) { if (i >= nk) break; m = fmaxf(m, S[qi][i]); }
#pragma unroll
            for (int o = 16; o > 0; o >>= 1) m = fmaxf(m, __shfl_xor_sync(0xffffffffu, m, o));
            float l = 0.f;
#pragma unroll
            for (int i = 0; i < NKMAX; i++) {
                if (i >= nk) break;
                float e = __expf(S[qi][i] - m);
                S[qi][i] = e;
                l += e;
            }
#pragma unroll
            for (int o = 16; o > 0; o >>= 1) l += __shfl_xor_sync(0xffffffffu, l, o);
            inv[qi] = 1.f / l;
        }

        // ---- write normalized probabilities into block-diagonal slice ----
#pragma unroll
        for (int qi = 0; qi < 4; qi++) {
            int q = q0 + qb + qi;
            if (q < qend) {
                size_t base = ((size_t)h * NTOK + q) * (size_t)NTOK + kstart;
                float iv = inv[qi];
#pragma unroll
                for (int i = 0; i < NKMAX; i++) {
                    if (i >= nk) break;
                    int k = (i << 5) + lane;
                    if (k < len) attn_out[base + k] = S[qi][i] * iv;
                }
            }
        }

        // ---- PV: lane owns output dim d = lane; broadcast p via shuffle ----
        float o0 = 0.f, o1 = 0.f, o2 = 0.f, o3 = 0.f;
#pragma unroll
        for (int i = 0; i < NKMAX; i++) {
            if (i >= nk) break;
#pragma unroll
            for (int j = 0; j < 32; j++) {
                float v = Vs[((i << 5) + j) * RPAD + lane];
                o0 += __shfl_sync(0xffffffffu, S[0][i], j) * v;
                o1 += __shfl_sync(0xffffffffu, S[1][i], j) * v;
                o2 += __shfl_sync(0xffffffffu, S[2][i], j) * v;
                o3 += __shfl_sync(0xffffffffu, S[3][i], j) * v;
            }
        }
        int q;
        q = q0 + qb + 0; if (q < qend) g_C[(size_t)q * DM + h * DK + lane] = o0 * inv[0];
        q = q0 + qb + 1; if (q < qend) g_C[(size_t)q * DM + h * DK + lane] = o1 * inv[1];
        q = q0 + qb + 2; if (q < qend) g_C[(size_t)q * DM + h * DK + lane] = o2 * inv[2];
        q = q0 + qb + 3; if (q < qend) g_C[(size_t)q * DM + h * DK + lane] = o3 * inv[3];
    }
}

// ---------------------------------------------------------------------------
extern "C" void kernel_launch(void* const* d_in, const int* in_sizes, int n_in,
                              void* d_out, int out_size) {
    const float* x_q      = (const float*)d_in[0];
    const float* x_kv     = (const float*)d_in[1];
    const int*   batch_q  = (const int*)d_in[2];   // jnp.int64 -> int32 (no x64 in JAX)
    const int*   batch_kv = (const int*)d_in[3];
    const float* Wq = (const float*)d_in[4];
    const float* bq = (const float*)d_in[5];
    const float* Wk = (const float*)d_in[6];
    const float* bk = (const float*)d_in[7];
    const float* Wv = (const float*)d_in[8];
    const float* bv = (const float*)d_in[9];
    const float* Wo = (const float*)d_in[10];
    const float* bo = (const float*)d_in[11];
    float* out = (float*)d_out;

    void *pQ, *pK, *pV, *pC;
    cudaGetSymbolAddress(&pQ, g_Q);
    cudaGetSymbolAddress(&pK, g_K);
    cudaGetSymbolAddress(&pV, g_V);
    cudaGetSymbolAddress(&pC, g_C);

    // 1) zero the whole output (attn region is ~94% exact zeros)
    zero_kernel<<<4096, 256>>>(out, (long long)out_size);

    // 2) Q/K/V projections
    dim3 ggrid(DM / 64, NTOK / 64);
    gemm_bias_kernel<<<ggrid, 256>>>(x_q,  Wq, bq, (float*)pQ);
    gemm_bias_kernel<<<ggrid, 256>>>(x_kv, Wk, bk, (float*)pK);
    gemm_bias_kernel<<<ggrid, 256>>>(x_kv, Wv, bv, (float*)pV);

    // 3) block-diagonal attention (+ attn matrix write + context)
    int smem = (2 * LMAX * RPAD + 32 * RPAD) * (int)sizeof(float);  // 152064 B
    cudaFuncSetAttribute(attn_kernel, cudaFuncAttributeMaxDynamicSharedMemorySize, smem);
    attn_kernel<<<dim3(NSEG, NH), 256, smem>>>(batch_q, batch_kv,
                                               out + (size_t)NTOK * DM);

    // 4) output projection into out[0 .. NTOK*DM)
    gemm_bias_kernel<<<ggrid, 256>>>((const float*)pC, Wo, bo, out);
}

// round 4
// speedup vs baseline: 1.0548x; 1.0548x over previous
#include <cuda_runtime.h>
#include <math.h>

#define NTOK 4096
#define DM   256
#define NH   8
#define DK   32
#define NSEG 16
#define LMAX 352            // mean seg len 256, sd ~15.5 -> ~6 sigma headroom; 106KB smem -> 2 blocks/SM
#define NKMAX (LMAX/32)     // 11 key-groups of 32
#define RPAD 36             // smem row pitch (32 data + 4 pad), keeps float4 alignment, conflict-free
#define QSPLIT 2            // query-range split per (seg, head)

// Scratch (device globals: no allocations allowed)
__device__ float g_Q[NTOK*DM];
__device__ float g_K[NTOK*DM];
__device__ float g_V[NTOK*DM];
__device__ float g_C[NTOK*DM];   // attention context before output projection

// ---------------------------------------------------------------------------
// Vectorized zero fill (attn output region is 537MB, ~94% exact zeros)
// ---------------------------------------------------------------------------
__global__ void zero_kernel(float* __restrict__ out, long long n) {
    long long i      = (long long)blockIdx.x * blockDim.x + threadIdx.x;
    long long stride = (long long)gridDim.x * blockDim.x;
    long long n4     = n >> 2;
    float4 z = make_float4(0.f, 0.f, 0.f, 0.f);
    float4* o4 = (float4*)out;
    for (long long j = i; j < n4; j += stride) o4[j] = z;
    long long tail = n4 << 2;
    if (i < (n - tail)) out[tail + i] = 0.f;
}

// ---------------------------------------------------------------------------
// Batched Linear: C[z][m,j] = sum_d A[z][m,d] * W[z][j,d] + b[z][j]
// blockIdx.z selects the problem. 64x64 tile, 256 threads, 4x4 microtile,
// k-chunk 16, double-buffered smem (one barrier per chunk).
// ---------------------------------------------------------------------------
struct GemmArgs {
    const float* A[3];
    const float* W[3];
    const float* b[3];
    float*       C[3];
};

__global__ void __launch_bounds__(256)
gemm_bias_kernel(GemmArgs args) {
    int z = blockIdx.z;
    const float* __restrict__ A    = args.A[z];
    const float* __restrict__ W    = args.W[z];
    const float* __restrict__ bias = args.b[z];
    float*       __restrict__ C    = args.C[z];

    __shared__ float As[2][16][68];   // [buf][k][m]
    __shared__ float Bs[2][16][68];   // [buf][k][j]
    int tid = threadIdx.x;
    int tx = tid & 15, ty = tid >> 4;
    int m0 = blockIdx.y << 6, j0 = blockIdx.x << 6;
    int lr = tid >> 2;           // 0..63 row within tile
    int lk = (tid & 3) << 2;     // 0,4,8,12 k within chunk

    float acc[4][4];
#pragma unroll
    for (int i = 0; i < 4; i++)
#pragma unroll
        for (int j = 0; j < 4; j++) acc[i][j] = 0.f;

    // preload chunk 0
    {
        float4 a = *(const float4*)&A[(size_t)(m0 + lr) * DM + lk];
        float4 b = *(const float4*)&W[(size_t)(j0 + lr) * DM + lk];
        As[0][lk + 0][lr] = a.x; As[0][lk + 1][lr] = a.y; As[0][lk + 2][lr] = a.z; As[0][lk + 3][lr] = a.w;
        Bs[0][lk + 0][lr] = b.x; Bs[0][lk + 1][lr] = b.y; Bs[0][lk + 2][lr] = b.z; Bs[0][lk + 3][lr] = b.w;
    }
    __syncthreads();

    const int NCH = DM / 16;   // 16 chunks
#pragma unroll 1
    for (int c = 0; c < NCH; c++) {
        int cur = c & 1, nxt = (c + 1) & 1;
        float4 an, bn;
        if (c + 1 < NCH) {
            int kc = (c + 1) << 4;
            an = *(const float4*)&A[(size_t)(m0 + lr) * DM + kc + lk];
            bn = *(const float4*)&W[(size_t)(j0 + lr) * DM + kc + lk];
        }
#pragma unroll
        for (int k = 0; k < 16; k++) {
            float av[4], bv[4];
#pragma unroll
            for (int i = 0; i < 4; i++) av[i] = As[cur][k][(ty << 2) + i];
#pragma unroll
            for (int j = 0; j < 4; j++) bv[j] = Bs[cur][k][(tx << 2) + j];
#pragma unroll
            for (int i = 0; i < 4; i++)
#pragma unroll
                for (int j = 0; j < 4; j++) acc[i][j] += av[i] * bv[j];
        }
        if (c + 1 < NCH) {
            As[nxt][lk + 0][lr] = an.x; As[nxt][lk + 1][lr] = an.y;
            As[nxt][lk + 2][lr] = an.z; As[nxt][lk + 3][lr] = an.w;
            Bs[nxt][lk + 0][lr] = bn.x; Bs[nxt][lk + 1][lr] = bn.y;
            Bs[nxt][lk + 2][lr] = bn.z; Bs[nxt][lk + 3][lr] = bn.w;
            __syncthreads();
        }
    }

    int j = j0 + (tx << 2);
    float4 bb = *(const float4*)&bias[j];
#pragma unroll
    for (int i = 0; i < 4; i++) {
        int m = m0 + (ty << 2) + i;
        float4 r = make_float4(acc[i][0] + bb.x, acc[i][1] + bb.y,
                               acc[i][2] + bb.z, acc[i][3] + bb.w);
        *(float4*)&C[(size_t)m * DM + j] = r;
    }
}

// ---------------------------------------------------------------------------
// Attention: one block per (segment, head, query-half). K/V staged in smem
// (zero padded to multiple of 32 rows). Each warp processes 4 queries;
// scores in registers, exact softmax, normalized probs written into the
// block-diagonal slice of the attn output, context into g_C.
// smem ~106KB -> 2 blocks/SM.
// ---------------------------------------------------------------------------
__global__ void __launch_bounds__(256)
attn_kernel(const int* __restrict__ batch_q,
            const int* __restrict__ batch_kv,
            float* __restrict__ attn_out) {   // base of attn region of d_out
    extern __shared__ float sm[];
    float* Ks = sm;                       // LMAX * RPAD
    float* Vs = sm + LMAX * RPAD;         // LMAX * RPAD
    float* Qs = sm + 2 * LMAX * RPAD;     // 32 * RPAD
    __shared__ int rng[4];

    int seg = blockIdx.x, h = blockIdx.y, qz = blockIdx.z;
    int tid = threadIdx.x, lane = tid & 31, warp = tid >> 5;

    if (tid < 4) {
        const int* arr = (tid < 2) ? batch_q : batch_kv;
        int target = seg + (tid & 1);
        int lo = 0, hi = NTOK;
        while (lo < hi) { int mid = (lo + hi) >> 1; if (arr[mid] < target) lo = mid + 1; else hi = mid; }
        rng[tid] = lo;
    }
    __syncthreads();
    int qstart = rng[0], qend = rng[1], kstart = rng[2], kend = rng[3];
    int len = kend - kstart;
    if (len <= 0 || qend <= qstart) return;
    if (len > LMAX) len = LMAX;           // unreachable for this distribution

    // this block's query sub-range
    int nq    = qend - qstart;
    int chunk = (nq + QSPLIT - 1) / QSPLIT;
    int qs = qstart + qz * chunk;
    int qe = qs + chunk; if (qe > qend) qe = qend;
    if (qs >= qe) return;

    int nk = (len + 31) >> 5;
    int rows = nk << 5;

    // stage K, V (zero padded rows beyond len)
    for (int idx = tid; idx < rows * DK; idx += 256) {
        int k = idx >> 5, d = idx & 31;
        float kv = 0.f, vv = 0.f;
        if (k < len) {
            size_t g = (size_t)(kstart + k) * DM + h * DK + d;
            kv = g_K[g]; vv = g_V[g];
        }
        Ks[k * RPAD + d] = kv;
        Vs[k * RPAD + d] = vv;
    }

    const float scale = 0.17677669529663689f;   // 1/sqrt(32)

    for (int q0 = qs; q0 < qe; q0 += 32) {
        __syncthreads();   // protect Qs reuse (also covers initial K/V staging)
        for (int idx = tid; idx < 32 * DK; idx += 256) {
            int r = idx >> 5, d = idx & 31;
            int q = q0 + r;
            Qs[r * RPAD + d] = (q < qe) ? g_Q[(size_t)q * DM + h * DK + d] : 0.f;
        }
        __syncthreads();

        int qb = warp << 2;   // this warp's 4 queries: q0+qb .. q0+qb+3
        float S[4][NKMAX];

        // ---- scores: lane owns key k = 32*i + lane, 4 queries ----
#pragma unroll
        for (int i = 0; i < NKMAX; i++) {
            if (i >= nk) break;
            int k = (i << 5) + lane;
            const float4* Kr = (const float4*)&Ks[k * RPAD];
            float a0 = 0.f, a1 = 0.f, a2 = 0.f, a3 = 0.f;
#pragma unroll
            for (int d4 = 0; d4 < 8; d4++) {
                float4 kv = Kr[d4];
                float4 v0 = *(const float4*)&Qs[(qb + 0) * RPAD + (d4 << 2)];
                float4 v1 = *(const float4*)&Qs[(qb + 1) * RPAD + (d4 << 2)];
                float4 v2 = *(const float4*)&Qs[(qb + 2) * RPAD + (d4 << 2)];
                float4 v3 = *(const float4*)&Qs[(qb + 3) * RPAD + (d4 << 2)];
                a0 += kv.x * v0.x + kv.y * v0.y + kv.z * v0.z + kv.w * v0.w;
                a1 += kv.x * v1.x + kv.y * v1.y + kv.z * v1.z + kv.w * v1.w;
                a2 += kv.x * v2.x + kv.y * v2.y + kv.z * v2.z + kv.w * v2.w;
                a3 += kv.x * v3.x + kv.y * v3.y + kv.z * v3.z + kv.w * v3.w;
            }
            bool ok = (k < len);
            S[0][i] = ok ? a0 * scale : -1e30f;
            S[1][i] = ok ? a1 * scale : -1e30f;
            S[2][i] = ok ? a2 * scale : -1e30f;
            S[3][i] = ok ? a3 * scale : -1e30f;
        }

        // ---- softmax (exact, register passes + warp reduce) ----
        float inv[4];
#pragma unroll
        for (int qi = 0; qi < 4; qi++) {
            float m = -1e30f;
#pragma unroll
            for (int i = 0; i < NKMAX; i++) { if (i >= nk) break; m = fmaxf(m, S[qi][i]); }
#pragma unroll
            for (int o = 16; o > 0; o >>= 1) m = fmaxf(m, __shfl_xor_sync(0xffffffffu, m, o));
            float l = 0.f;
#pragma unroll
            for (int i = 0; i < NKMAX; i++) {
                if (i >= nk) break;
                float e = __expf(S[qi][i] - m);
                S[qi][i] = e;
                l += e;
            }
#pragma unroll
            for (int o = 16; o > 0; o >>= 1) l += __shfl_xor_sync(0xffffffffu, l, o);
            inv[qi] = 1.f / l;
        }

        // ---- write normalized probabilities into block-diagonal slice ----
#pragma unroll
        for (int qi = 0; qi < 4; qi++) {
            int q = q0 + qb + qi;
            if (q < qe) {
                size_t base = ((size_t)h * NTOK + q) * (size_t)NTOK + kstart;
                float iv = inv[qi];
#pragma unroll
                for (int i = 0; i < NKMAX; i++) {
                    if (i >= nk) break;
                    int k = (i << 5) + lane;
                    if (k < len) attn_out[base + k] = S[qi][i] * iv;
                }
            }
        }

        // ---- PV: lane owns output dim d = lane; broadcast p via shuffle ----
        float o0 = 0.f, o1 = 0.f, o2 = 0.f, o3 = 0.f;
#pragma unroll
        for (int i = 0; i < NKMAX; i++) {
            if (i >= nk) break;
#pragma unroll
            for (int j = 0; j < 32; j++) {
                float v = Vs[((i << 5) + j) * RPAD + lane];
                o0 += __shfl_sync(0xffffffffu, S[0][i], j) * v;
                o1 += __shfl_sync(0xffffffffu, S[1][i], j) * v;
                o2 += __shfl_sync(0xffffffffu, S[2][i], j) * v;
                o3 += __shfl_sync(0xffffffffu, S[3][i], j) * v;
            }
        }
        int q;
        q = q0 + qb + 0; if (q < qe) g_C[(size_t)q * DM + h * DK + lane] = o0 * inv[0];
        q = q0 + qb + 1; if (q < qe) g_C[(size_t)q * DM + h * DK + lane] = o1 * inv[1];
        q = q0 + qb + 2; if (q < qe) g_C[(size_t)q * DM + h * DK + lane] = o2 * inv[2];
        q = q0 + qb + 3; if (q < qe) g_C[(size_t)q * DM + h * DK + lane] = o3 * inv[3];
    }
}

// ---------------------------------------------------------------------------
extern "C" void kernel_launch(void* const* d_in, const int* in_sizes, int n_in,
                              void* d_out, int out_size) {
    const float* x_q      = (const float*)d_in[0];
    const float* x_kv     = (const float*)d_in[1];
    const int*   batch_q  = (const int*)d_in[2];   // jnp.int64 -> int32 (no x64 in JAX)
    const int*   batch_kv = (const int*)d_in[3];
    const float* Wq = (const float*)d_in[4];
    const float* bq = (const float*)d_in[5];
    const float* Wk = (const float*)d_in[6];
    const float* bk = (const float*)d_in[7];
    const float* Wv = (const float*)d_in[8];
    const float* bv = (const float*)d_in[9];
    const float* Wo = (const float*)d_in[10];
    const float* bo = (const float*)d_in[11];
    float* out = (float*)d_out;

    void *pQ, *pK, *pV, *pC;
    cudaGetSymbolAddress(&pQ, g_Q);
    cudaGetSymbolAddress(&pK, g_K);
    cudaGetSymbolAddress(&pV, g_V);
    cudaGetSymbolAddress(&pC, g_C);

    // 1) zero the whole output (attn region is ~94% exact zeros)
    zero_kernel<<<4096, 256>>>(out, (long long)out_size);

    // 2) Q/K/V projections in ONE launch (grid.z = 3)
    GemmArgs qkv;
    qkv.A[0] = x_q;  qkv.A[1] = x_kv; qkv.A[2] = x_kv;
    qkv.W[0] = Wq;   qkv.W[1] = Wk;   qkv.W[2] = Wv;
    qkv.b[0] = bq;   qkv.b[1] = bk;   qkv.b[2] = bv;
    qkv.C[0] = (float*)pQ; qkv.C[1] = (float*)pK; qkv.C[2] = (float*)pV;
    dim3 ggrid(DM / 64, NTOK / 64, 3);
    gemm_bias_kernel<<<ggrid, 256>>>(qkv);

    // 3) block-diagonal attention (+ attn matrix write + context)
    int smem = (2 * LMAX * RPAD + 32 * RPAD) * (int)sizeof(float);  // 105984 B -> 2 blocks/SM
    cudaFuncSetAttribute(attn_kernel, cudaFuncAttributeMaxDynamicSharedMemorySize, smem);
    attn_kernel<<<dim3(NSEG, NH, QSPLIT), 256, smem>>>(batch_q, batch_kv,
                                                       out + (size_t)NTOK * DM);

    // 4) output projection into out[0 .. NTOK*DM)
    GemmArgs og;
    og.A[0] = (const float*)pC; og.W[0] = Wo; og.b[0] = bo; og.C[0] = out;
    og.A[1] = og.A[2] = nullptr; og.W[1] = og.W[2] = nullptr;
    og.b[1] = og.b[2] = nullptr; og.C[1] = og.C[2] = nullptr;
    gemm_bias_kernel<<<dim3(DM / 64, NTOK / 64, 1), 256>>>(og);
}